// round 10
// baseline (speedup 1.0000x reference)
#include <cuda_runtime.h>
#include <math.h>

#define NPTS 65536
#define NS 16
#define C 256
#define MTOT (NPTS*NS)
#define EPS 1e-5f

typedef unsigned long long ull;

__device__ __forceinline__ ull pack2(float lo, float hi) {
    ull r; asm("mov.b64 %0, {%1, %2};" : "=l"(r) : "f"(lo), "f"(hi)); return r;
}
__device__ __forceinline__ void fma2(ull& d, ull a, ull b) {
    asm("fma.rn.f32x2 %0, %1, %2, %3;" : "=l"(d) : "l"(a), "l"(b), "l"(d));
}
__device__ __forceinline__ float2 unpack2(ull v) {
    float2 f; asm("mov.b64 {%0, %1}, %2;" : "=f"(f.x), "=f"(f.y) : "l"(v)); return f;
}

__device__ float g_xq[NPTS*C];
__device__ float g_xk[NPTS*C];
__device__ float g_xv[NPTS*C];
__device__ float g_w2[NPTS*NS*32];
__device__ float g_v3[MTOT*3];
__device__ float g_sum_p[3], g_ssq_p[3];
__device__ float g_sum_1[C], g_ssq_1[C];
__device__ float g_sum_2[32], g_ssq_2[32];

__global__ void k_zero() {
    int t = threadIdx.x;
    if (t < 3)  { g_sum_p[t] = 0.f; g_ssq_p[t] = 0.f; }
    if (t < C)  { g_sum_1[t] = 0.f; g_ssq_1[t] = 0.f; }
    if (t < 32) { g_sum_2[t] = 0.f; g_ssq_2[t] = 0.f; }
}

// ---------------- qkv SGEMM (FFMA2) + fused statp/v3 ----------------
__global__ __launch_bounds__(256) void k_qkv_statp(
        const float* __restrict__ x, const float* __restrict__ p,
        const int* __restrict__ idx,
        const float* __restrict__ wq, const float* __restrict__ bq,
        const float* __restrict__ wk, const float* __restrict__ bk,
        const float* __restrict__ wv, const float* __restrict__ bv,
        const float* __restrict__ wp1, const float* __restrict__ bp1) {
    const int t = threadIdx.x;
    if (blockIdx.x == 6) {
        float W[9], B[3];
#pragma unroll
        for (int q = 0; q < 9; q++) W[q] = wp1[q];
#pragma unroll
        for (int q = 0; q < 3; q++) B[q] = bp1[q];
        float s[3] = {0,0,0}, ss[3] = {0,0,0};
        for (int m = blockIdx.y*256 + t; m < MTOT; m += 512*256) {
            int i = m >> 4;
            int nb = idx[m];
            float d0 = p[nb*3+0]-p[i*3+0], d1 = p[nb*3+1]-p[i*3+1], d2 = p[nb*3+2]-p[i*3+2];
#pragma unroll
            for (int d = 0; d < 3; d++) {
                float v = W[d*3+0]*d0 + W[d*3+1]*d1 + W[d*3+2]*d2 + B[d];
                g_v3[(size_t)m*3 + d] = v;
                s[d] += v; ss[d] += v*v;
            }
        }
#pragma unroll
        for (int off = 16; off > 0; off >>= 1)
#pragma unroll
            for (int d = 0; d < 3; d++) {
                s[d]  += __shfl_down_sync(0xffffffffu, s[d],  off);
                ss[d] += __shfl_down_sync(0xffffffffu, ss[d], off);
            }
        if ((t & 31) == 0)
#pragma unroll
            for (int d = 0; d < 3; d++) {
                atomicAdd(&g_sum_p[d], s[d]); atomicAdd(&g_ssq_p[d], ss[d]);
            }
        return;
    }
    __shared__ float As[16][132];
    __shared__ float Bs[16][132];
    const int tx = t & 15, ty = t >> 4;
    const int m0 = blockIdx.y * 128, n0 = blockIdx.x * 128;
    const float* wsel; const float* bsel; float* dst;
    if (n0 < 256)      { wsel = wq; bsel = bq; dst = g_xq; }
    else if (n0 < 512) { wsel = wk; bsel = bk; dst = g_xk; }
    else               { wsel = wv; bsel = bv; dst = g_xv; }
    const int rb = n0 & 255;
    ull acc2[8][4];
#pragma unroll
    for (int ii = 0; ii < 8; ii++)
#pragma unroll
        for (int jj = 0; jj < 4; jj++) acc2[ii][jj] = 0ull;
    const int lrow = t >> 2, lk4 = (t & 3) << 2;
    for (int k0 = 0; k0 < 256; k0 += 16) {
#pragma unroll
        for (int h = 0; h < 2; h++) {
            int r = lrow + h*64;
            float4 va = *(const float4*)(x + (size_t)(m0 + r)*256 + k0 + lk4);
            As[lk4+0][r] = va.x; As[lk4+1][r] = va.y; As[lk4+2][r] = va.z; As[lk4+3][r] = va.w;
            float4 vb = *(const float4*)(wsel + (size_t)(rb + r)*256 + k0 + lk4);
            Bs[lk4+0][r] = vb.x; Bs[lk4+1][r] = vb.y; Bs[lk4+2][r] = vb.z; Bs[lk4+3][r] = vb.w;
        }
        __syncthreads();
#pragma unroll
        for (int k = 0; k < 16; k++) {
            float a[8];
            *(float4*)&a[0] = *(const float4*)&As[k][ty*4];
            *(float4*)&a[4] = *(const float4*)&As[k][ty*4 + 64];
            ull b2[4];
            {
                ulonglong2 u0 = *(const ulonglong2*)&Bs[k][tx*4];
                ulonglong2 u1 = *(const ulonglong2*)&Bs[k][tx*4 + 64];
                b2[0] = u0.x; b2[1] = u0.y; b2[2] = u1.x; b2[3] = u1.y;
            }
            ull a2[8];
#pragma unroll
            for (int ii = 0; ii < 8; ii++) a2[ii] = pack2(a[ii], a[ii]);
#pragma unroll
            for (int ii = 0; ii < 8; ii++)
#pragma unroll
                for (int jj = 0; jj < 4; jj++) fma2(acc2[ii][jj], a2[ii], b2[jj]);
        }
        __syncthreads();
    }
    float bias[8];
#pragma unroll
    for (int jj = 0; jj < 8; jj++)
        bias[jj] = bsel[rb + tx*4 + ((jj >> 2) << 6) + (jj & 3)];
#pragma unroll
    for (int ii = 0; ii < 8; ii++) {
        int row = m0 + ty*4 + (ii & 3) + ((ii >> 2) << 6);
#pragma unroll
        for (int jh = 0; jh < 2; jh++) {
            float2 lo = unpack2(acc2[ii][jh*2]);
            float2 hi = unpack2(acc2[ii][jh*2+1]);
            float4 o = {lo.x + bias[jh*4], lo.y + bias[jh*4+1], hi.x + bias[jh*4+2], hi.y + bias[jh*4+3]};
            *(float4*)(dst + (size_t)row*256 + rb + tx*4 + (jh << 6)) = o;
        }
    }
}

// ---------------- BN1 stats: float4 gathers, 64 thr/point ----------------
__global__ __launch_bounds__(256) void k_stat1(const int* __restrict__ idx,
        const float* __restrict__ gp, const float* __restrict__ btp,
        const float* __restrict__ wp2, const float* __restrict__ bp2) {
    __shared__ float sR3[4][48];
    __shared__ int   sIdxs[4][16];
    __shared__ float sTmp[2048];
    const int t = threadIdx.x;
    const int sub = t >> 6, cg = t & 63, c0 = cg << 2;
    const float invM = 1.f / (float)MTOT;
    float bns[3], bnh[3];
#pragma unroll
    for (int d = 0; d < 3; d++) {
        float m = g_sum_p[d]*invM;
        float v = fmaxf(g_ssq_p[d]*invM - m*m, 0.f);
        bns[d] = gp[d]*rsqrtf(v+EPS); bnh[d] = btp[d] - m*bns[d];
    }
    float w20[4], w21[4], w22[4], bpc[4];
#pragma unroll
    for (int q = 0; q < 4; q++) {
        w20[q] = wp2[(c0+q)*3+0]; w21[q] = wp2[(c0+q)*3+1]; w22[q] = wp2[(c0+q)*3+2];
        bpc[q] = bp2[c0+q];
    }
    float s[4] = {0,0,0,0}, ss[4] = {0,0,0,0};
    const int i0 = blockIdx.x * 16;
    for (int it = 0; it < 4; it++) {
        const int i = i0 + it*4 + sub;
        __syncthreads();
        if (cg < 16) sIdxs[sub][cg] = idx[i*NS + cg];
        else if (cg < 32) {
            int j = cg - 16;
            const float* vp = g_v3 + ((size_t)i*NS + j)*3;
            sR3[sub][j*3+0] = fmaxf(bns[0]*vp[0] + bnh[0], 0.f);
            sR3[sub][j*3+1] = fmaxf(bns[1]*vp[1] + bnh[1], 0.f);
            sR3[sub][j*3+2] = fmaxf(bns[2]*vp[2] + bnh[2], 0.f);
        }
        __syncthreads();
        float4 xq4 = __ldg((const float4*)(g_xq + (size_t)i*C + c0));
#pragma unroll
        for (int j = 0; j < 16; j++) {
            int nb = sIdxs[sub][j];
            float r0 = sR3[sub][j*3], r1 = sR3[sub][j*3+1], r2 = sR3[sub][j*3+2];
            float4 xk4 = __ldg((const float4*)(g_xk + (size_t)nb*C + c0));
            float w;
            w = xk4.x - xq4.x + w20[0]*r0 + w21[0]*r1 + w22[0]*r2 + bpc[0]; s[0] += w; ss[0] += w*w;
            w = xk4.y - xq4.y + w20[1]*r0 + w21[1]*r1 + w22[1]*r2 + bpc[1]; s[1] += w; ss[1] += w*w;
            w = xk4.z - xq4.z + w20[2]*r0 + w21[2]*r1 + w22[2]*r2 + bpc[2]; s[2] += w; ss[2] += w*w;
            w = xk4.w - xq4.w + w20[3]*r0 + w21[3]*r1 + w22[3]*r2 + bpc[3]; s[3] += w; ss[3] += w*w;
        }
    }
    __syncthreads();
#pragma unroll
    for (int q = 0; q < 4; q++) {
        sTmp[sub*256 + c0 + q] = s[q];
        sTmp[1024 + sub*256 + c0 + q] = ss[q];
    }
    __syncthreads();
    float a = sTmp[t] + sTmp[256+t] + sTmp[512+t] + sTmp[768+t];
    atomicAdd(&g_sum_1[t], a);
    float b = sTmp[1024+t] + sTmp[1280+t] + sTmp[1536+t] + sTmp[1792+t];
    atomicAdd(&g_ssq_1[t], b);
}

// ---------------- w2 GEMM: 128-row tiles, (4x4) register-tiled FFMA2 ----------------
// smem floats: sW[128*260]=33280 | sB[32*260]=8320 | sXq[2048] | sR3[384] | sIdx[128]
#define K6_SMEM_FLOATS (33280 + 8320 + 2048 + 384 + 128)
__global__ __launch_bounds__(256, 1) void k_w2(const int* __restrict__ idx,
        const float* __restrict__ gp, const float* __restrict__ btp,
        const float* __restrict__ wp2, const float* __restrict__ bp2,
        const float* __restrict__ ww1, const float* __restrict__ bw1,
        const float* __restrict__ g1, const float* __restrict__ b1) {
    extern __shared__ float sm[];
    float* sW  = sm;                    // [128][260]
    float* sB  = sm + 33280;            // [32][260]
    float* sXq = sm + 41600;            // [8][256]
    float* sR3 = sm + 43648;            // [384]
    int*   sIdx = (int*)(sm + 44032);   // [128]
    const int t = threadIdx.x;
    for (int e = t; e < 8192; e += 256) sB[(e>>8)*260 + (e&255)] = ww1[e];
    const int rgrp = t >> 6, cg = t & 63, c0 = cg << 2;
    const float invM = 1.f / (float)MTOT;
    float bns[3], bnh[3];
#pragma unroll
    for (int d = 0; d < 3; d++) {
        float m = g_sum_p[d]*invM;
        float v = fmaxf(g_ssq_p[d]*invM - m*m, 0.f);
        bns[d] = gp[d]*rsqrtf(v+EPS); bnh[d] = btp[d] - m*bns[d];
    }
    float s1[4], h1[4], w20[4], w21[4], w22[4], bpc[4];
#pragma unroll
    for (int q = 0; q < 4; q++) {
        float mean = g_sum_1[c0+q]*invM;
        float var  = fmaxf(g_ssq_1[c0+q]*invM - mean*mean, 0.f);
        s1[q] = g1[c0+q]*rsqrtf(var+EPS); h1[q] = b1[c0+q] - mean*s1[q];
        w20[q] = wp2[(c0+q)*3+0]; w21[q] = wp2[(c0+q)*3+1]; w22[q] = wp2[(c0+q)*3+2];
        bpc[q] = bp2[c0+q];
    }
    const int rg = t >> 3, og = t & 7;   // thread: rows rg+32a, ocs og+8b
    float bwv[4];
#pragma unroll
    for (int b = 0; b < 4; b++) bwv[b] = bw1[og + 8*b];
    float acs[4] = {0,0,0,0}, acss[4] = {0,0,0,0};
    const int i0 = blockIdx.x * 64;

    for (int pp = 0; pp < 8; pp++) {
        const int iB = i0 + pp*8;       // 8 points per tile
        __syncthreads();
        if (t < 128) sIdx[t] = idx[iB*NS + t];
        for (int e = t; e < 384; e += 256) {
            int d = e % 3;
            sR3[e] = fmaxf(bns[d]*g_v3[(size_t)iB*48 + e] + bnh[d], 0.f);
        }
#pragma unroll
        for (int h = 0; h < 2; h++) {
            int e = h*256 + t;          // 512 float4 = 8 pts x 64
            ((float4*)sXq)[e] = __ldg((const float4*)(g_xq + (size_t)(iB + (e>>6))*C) + (e & 63));
        }
        __syncthreads();
        // build sW[128][260]: gather + bn1 + relu
#pragma unroll 4
        for (int m = 0; m < 32; m++) {
            int row = m*4 + rgrp;
            int nb = sIdx[row];
            float r0 = sR3[row*3], r1 = sR3[row*3+1], rr2 = sR3[row*3+2];
            float4 xk4 = __ldg((const float4*)(g_xk + (size_t)nb*C + c0));
            const float4 xq4 = *(const float4*)(sXq + ((row >> 4) << 8) + c0);
            float4 u;
            u.x = fmaxf(s1[0]*(xk4.x - xq4.x + w20[0]*r0 + w21[0]*r1 + w22[0]*rr2 + bpc[0]) + h1[0], 0.f);
            u.y = fmaxf(s1[1]*(xk4.y - xq4.y + w20[1]*r0 + w21[1]*r1 + w22[1]*rr2 + bpc[1]) + h1[1], 0.f);
            u.z = fmaxf(s1[2]*(xk4.z - xq4.z + w20[2]*r0 + w21[2]*r1 + w22[2]*rr2 + bpc[2]) + h1[2], 0.f);
            u.w = fmaxf(s1[3]*(xk4.w - xq4.w + w20[3]*r0 + w21[3]*r1 + w22[3]*rr2 + bpc[3]) + h1[3], 0.f);
            *(float4*)(sW + row*260 + c0) = u;
        }
        __syncthreads();
        // GEMM: 4 rows x 4 oc per thread
        ull acc[4][4];
#pragma unroll
        for (int a = 0; a < 4; a++)
#pragma unroll
            for (int b = 0; b < 4; b++) acc[a][b] = 0ull;
        const ulonglong2* pa0 = (const ulonglong2*)(sW + (rg     )*260);
        const ulonglong2* pa1 = (const ulonglong2*)(sW + (rg + 32)*260);
        const ulonglong2* pa2 = (const ulonglong2*)(sW + (rg + 64)*260);
        const ulonglong2* pa3 = (const ulonglong2*)(sW + (rg + 96)*260);
        const ulonglong2* pw0 = (const ulonglong2*)(sB + (og     )*260);
        const ulonglong2* pw1 = (const ulonglong2*)(sB + (og +  8)*260);
        const ulonglong2* pw2 = (const ulonglong2*)(sB + (og + 16)*260);
        const ulonglong2* pw3 = (const ulonglong2*)(sB + (og + 24)*260);
#pragma unroll 4
        for (int k4 = 0; k4 < 64; k4++) {
            ulonglong2 a0 = pa0[k4], a1 = pa1[k4], a2 = pa2[k4], a3 = pa3[k4];
            ulonglong2 w0 = pw0[k4];
            fma2(acc[0][0], a0.x, w0.x); fma2(acc[0][0], a0.y, w0.y);
            fma2(acc[1][0], a1.x, w0.x); fma2(acc[1][0], a1.y, w0.y);
            fma2(acc[2][0], a2.x, w0.x); fma2(acc[2][0], a2.y, w0.y);
            fma2(acc[3][0], a3.x, w0.x); fma2(acc[3][0], a3.y, w0.y);
            ulonglong2 w1 = pw1[k4];
            fma2(acc[0][1], a0.x, w1.x); fma2(acc[0][1], a0.y, w1.y);
            fma2(acc[1][1], a1.x, w1.x); fma2(acc[1][1], a1.y, w1.y);
            fma2(acc[2][1], a2.x, w1.x); fma2(acc[2][1], a2.y, w1.y);
            fma2(acc[3][1], a3.x, w1.x); fma2(acc[3][1], a3.y, w1.y);
            ulonglong2 w2 = pw2[k4];
            fma2(acc[0][2], a0.x, w2.x); fma2(acc[0][2], a0.y, w2.y);
            fma2(acc[1][2], a1.x, w2.x); fma2(acc[1][2], a1.y, w2.y);
            fma2(acc[2][2], a2.x, w2.x); fma2(acc[2][2], a2.y, w2.y);
            fma2(acc[3][2], a3.x, w2.x); fma2(acc[3][2], a3.y, w2.y);
            ulonglong2 w3 = pw3[k4];
            fma2(acc[0][3], a0.x, w3.x); fma2(acc[0][3], a0.y, w3.y);
            fma2(acc[1][3], a1.x, w3.x); fma2(acc[1][3], a1.y, w3.y);
            fma2(acc[2][3], a2.x, w3.x); fma2(acc[2][3], a2.y, w3.y);
            fma2(acc[3][3], a3.x, w3.x); fma2(acc[3][3], a3.y, w3.y);
        }
#pragma unroll
        for (int a = 0; a < 4; a++) {
            int row = rg + 32*a;
#pragma unroll
            for (int b = 0; b < 4; b++) {
                int oc = og + 8*b;
                float2 f = unpack2(acc[a][b]);
                float v = f.x + f.y + bwv[b];
                g_w2[(size_t)iB*512 + row*32 + oc] = v;
                acs[b] += v; acss[b] += v*v;
            }
        }
    }
    // BN2 stats reduce (reuse sW)
    __syncthreads();
#pragma unroll
    for (int b = 0; b < 4; b++) {
        sW[t*4 + b] = acs[b];
        sW[1024 + t*4 + b] = acss[b];
    }
    __syncthreads();
    if (t < 32) {
        int g = t & 7, v = t >> 3;
        float a = 0.f, bb = 0.f;
#pragma unroll 8
        for (int u = 0; u < 32; u++) {
            a  += sW[(g + 8*u)*4 + v];
            bb += sW[1024 + (g + 8*u)*4 + v];
        }
        atomicAdd(&g_sum_2[t], a);
        atomicAdd(&g_ssq_2[t], bb);
    }
}

// ---------------- bn2->relu->ww2(regs)->softmax->weighted sum ----------------
__global__ __launch_bounds__(256) void k_out(const int* __restrict__ idx,
        const float* __restrict__ gp, const float* __restrict__ btp,
        const float* __restrict__ wp2, const float* __restrict__ bp2,
        const float* __restrict__ ww2, const float* __restrict__ bw2,
        const float* __restrict__ g2, const float* __restrict__ b2,
        float* __restrict__ out) {
    __shared__ float sU[32*34];
    __shared__ float sW3[32*33];
    __shared__ int   sIdx[32];
    __shared__ float sR3[96];
    const int t = threadIdx.x;
    const int cm = t & 31;
    const float invM = 1.f / (float)MTOT;
    float s2, h2;
    {
        float m = g_sum_2[cm]*invM;
        float v = fmaxf(g_ssq_2[cm]*invM - m*m, 0.f);
        s2 = g2[cm]*rsqrtf(v+EPS); h2 = b2[cm] - m*s2;
    }
    ull wreg[16];
    {
        const ulonglong2* wp = (const ulonglong2*)(ww2 + cm*32);
#pragma unroll
        for (int q = 0; q < 8; q++) {
            ulonglong2 v = __ldg(wp + q);
            wreg[q*2] = v.x; wreg[q*2+1] = v.y;
        }
    }
    const float bw2c = bw2[cm];
    float bns[3], bnh[3];
#pragma unroll
    for (int d = 0; d < 3; d++) {
        float m = g_sum_p[d]*invM;
        float v = fmaxf(g_ssq_p[d]*invM - m*m, 0.f);
        bns[d] = gp[d]*rsqrtf(v+EPS); bnh[d] = btp[d] - m*bns[d];
    }
    const float w20 = wp2[t*3+0], w21 = wp2[t*3+1], w22 = wp2[t*3+2], bpc = bp2[t];
    const int i0 = blockIdx.x * 16;

    for (int pp = 0; pp < 8; pp++) {
        const int iA = i0 + pp*2;
        __syncthreads();
        if (t < 32) sIdx[t] = idx[iA*NS + t];
        else if (t < 128) {
            int m = t - 32, d = m % 3;
            sR3[m] = fmaxf(bns[d]*g_v3[(size_t)iA*48 + m] + bnh[d], 0.f);
        }
#pragma unroll
        for (int rep = 0; rep < 4; rep++) {
            int linear = rep*256 + t;
            float v = g_w2[(size_t)iA*512 + linear];
            sU[(linear >> 5)*34 + cm] = fmaxf(s2*v + h2, 0.f);
        }
        __syncthreads();
#pragma unroll
        for (int rep = 0; rep < 4; rep++) {
            int jrow = rep*8 + (t >> 5);
            const ull* up = (const ull*)(sU + jrow*34);
            ull acc = 0ull;
#pragma unroll
            for (int k2 = 0; k2 < 16; k2++) fma2(acc, up[k2], wreg[k2]);
            float2 f = unpack2(acc);
            sW3[jrow*33 + cm] = f.x + f.y + bw2c;
        }
        __syncthreads();
        if (t < 64) {
            int pt = t >> 5, c = t & 31;
            int base = pt * 16;
            float mx = -1e30f;
#pragma unroll
            for (int j = 0; j < 16; j++) mx = fmaxf(mx, sW3[(base+j)*33 + c]);
            float sum = 0.f;
#pragma unroll
            for (int j = 0; j < 16; j++) {
                float e = __expf(sW3[(base+j)*33 + c] - mx);
                sW3[(base+j)*33 + c] = e; sum += e;
            }
            float inv = 1.f / sum;
#pragma unroll
            for (int j = 0; j < 16; j++) sW3[(base+j)*33 + c] *= inv;
        }
        __syncthreads();
#pragma unroll
        for (int pt = 0; pt < 2; pt++) {
            float acc = 0.f;
#pragma unroll
            for (int j = 0; j < 16; j++) {
                int rj = pt*16 + j;
                int nb = sIdx[rj];
                float pr = w20*sR3[rj*3] + w21*sR3[rj*3+1] + w22*sR3[rj*3+2] + bpc;
                acc += (g_xv[(size_t)nb*C + t] + pr) * sW3[rj*33 + cm];
            }
            out[(size_t)(iA+pt)*C + t] = acc;
        }
    }
}

extern "C" void kernel_launch(void* const* d_in, const int* in_sizes, int n_in,
                              void* d_out, int out_size) {
    const float* p   = (const float*)d_in[0];
    const float* x   = (const float*)d_in[1];
    const int*   idx = (const int*)d_in[2];
    const float* wq  = (const float*)d_in[3];
    const float* bq  = (const float*)d_in[4];
    const float* wk  = (const float*)d_in[5];
    const float* bk  = (const float*)d_in[6];
    const float* wv  = (const float*)d_in[7];
    const float* bv  = (const float*)d_in[8];
    const float* wp1 = (const float*)d_in[9];
    const float* bp1 = (const float*)d_in[10];
    const float* gp  = (const float*)d_in[11];
    const float* btp = (const float*)d_in[12];
    const float* wp2 = (const float*)d_in[13];
    const float* bp2 = (const float*)d_in[14];
    const float* g1  = (const float*)d_in[15];
    const float* b1  = (const float*)d_in[16];
    const float* ww1 = (const float*)d_in[17];
    const float* bw1 = (const float*)d_in[18];
    const float* g2  = (const float*)d_in[19];
    const float* b2  = (const float*)d_in[20];
    const float* ww2 = (const float*)d_in[21];
    const float* bw2 = (const float*)d_in[22];
    float* out = (float*)d_out;

    cudaFuncSetAttribute(k_w2, cudaFuncAttributeMaxDynamicSharedMemorySize,
                         K6_SMEM_FLOATS * (int)sizeof(float));

    k_zero<<<1, 256>>>();
    k_qkv_statp<<<dim3(7, 512), 256>>>(x, p, idx, wq, bq, wk, bk, wv, bv, wp1, bp1);
    k_stat1<<<4096, 256>>>(idx, gp, btp, wp2, bp2);
    k_w2<<<1024, 256, K6_SMEM_FLOATS * sizeof(float)>>>(idx, gp, btp, wp2, bp2, ww1, bw1, g1, b1);
    k_out<<<4096, 256>>>(idx, gp, btp, wp2, bp2, ww2, bw2, g2, b2, out);
}

// round 11
// speedup vs baseline: 1.1452x; 1.1452x over previous
#include <cuda_runtime.h>
#include <math.h>

#define NPTS 65536
#define NS 16
#define C 256
#define MTOT (NPTS*NS)
#define EPS 1e-5f

typedef unsigned long long ull;

__device__ __forceinline__ ull pack2(float lo, float hi) {
    ull r; asm("mov.b64 %0, {%1, %2};" : "=l"(r) : "f"(lo), "f"(hi)); return r;
}
__device__ __forceinline__ void fma2(ull& d, ull a, ull b) {
    asm("fma.rn.f32x2 %0, %1, %2, %3;" : "=l"(d) : "l"(a), "l"(b), "l"(d));
}
__device__ __forceinline__ float2 unpack2(ull v) {
    float2 f; asm("mov.b64 {%0, %1}, %2;" : "=f"(f.x), "=f"(f.y) : "l"(v)); return f;
}
__device__ __forceinline__ void bar_sync(int id) {
    asm volatile("bar.sync %0, %1;" :: "r"(id), "r"(256) : "memory");
}
__device__ __forceinline__ void bar_arrive(int id) {
    asm volatile("bar.arrive %0, %1;" :: "r"(id), "r"(256) : "memory");
}

__device__ float g_xq[NPTS*C];
__device__ float g_xk[NPTS*C];
__device__ float g_xv[NPTS*C];
__device__ float g_w2[NPTS*NS*32];
__device__ float g_v3[MTOT*3];
__device__ float g_sum_p[3], g_ssq_p[3];
__device__ float g_sum_1[C], g_ssq_1[C];
__device__ float g_sum_2[32], g_ssq_2[32];

__global__ void k_zero() {
    int t = threadIdx.x;
    if (t < 3)  { g_sum_p[t] = 0.f; g_ssq_p[t] = 0.f; }
    if (t < C)  { g_sum_1[t] = 0.f; g_ssq_1[t] = 0.f; }
    if (t < 32) { g_sum_2[t] = 0.f; g_ssq_2[t] = 0.f; }
}

// ---------------- qkv SGEMM (FFMA2) + fused statp/v3 ----------------
__global__ __launch_bounds__(256) void k_qkv_statp(
        const float* __restrict__ x, const float* __restrict__ p,
        const int* __restrict__ idx,
        const float* __restrict__ wq, const float* __restrict__ bq,
        const float* __restrict__ wk, const float* __restrict__ bk,
        const float* __restrict__ wv, const float* __restrict__ bv,
        const float* __restrict__ wp1, const float* __restrict__ bp1) {
    const int t = threadIdx.x;
    if (blockIdx.x == 6) {
        float W[9], B[3];
#pragma unroll
        for (int q = 0; q < 9; q++) W[q] = wp1[q];
#pragma unroll
        for (int q = 0; q < 3; q++) B[q] = bp1[q];
        float s[3] = {0,0,0}, ss[3] = {0,0,0};
        for (int m = blockIdx.y*256 + t; m < MTOT; m += 512*256) {
            int i = m >> 4;
            int nb = idx[m];
            float d0 = p[nb*3+0]-p[i*3+0], d1 = p[nb*3+1]-p[i*3+1], d2 = p[nb*3+2]-p[i*3+2];
#pragma unroll
            for (int d = 0; d < 3; d++) {
                float v = W[d*3+0]*d0 + W[d*3+1]*d1 + W[d*3+2]*d2 + B[d];
                g_v3[(size_t)m*3 + d] = v;
                s[d] += v; ss[d] += v*v;
            }
        }
#pragma unroll
        for (int off = 16; off > 0; off >>= 1)
#pragma unroll
            for (int d = 0; d < 3; d++) {
                s[d]  += __shfl_down_sync(0xffffffffu, s[d],  off);
                ss[d] += __shfl_down_sync(0xffffffffu, ss[d], off);
            }
        if ((t & 31) == 0)
#pragma unroll
            for (int d = 0; d < 3; d++) {
                atomicAdd(&g_sum_p[d], s[d]); atomicAdd(&g_ssq_p[d], ss[d]);
            }
        return;
    }
    __shared__ float As[16][132];
    __shared__ float Bs[16][132];
    const int tx = t & 15, ty = t >> 4;
    const int m0 = blockIdx.y * 128, n0 = blockIdx.x * 128;
    const float* wsel; const float* bsel; float* dst;
    if (n0 < 256)      { wsel = wq; bsel = bq; dst = g_xq; }
    else if (n0 < 512) { wsel = wk; bsel = bk; dst = g_xk; }
    else               { wsel = wv; bsel = bv; dst = g_xv; }
    const int rb = n0 & 255;
    ull acc2[8][4];
#pragma unroll
    for (int ii = 0; ii < 8; ii++)
#pragma unroll
        for (int jj = 0; jj < 4; jj++) acc2[ii][jj] = 0ull;
    const int lrow = t >> 2, lk4 = (t & 3) << 2;
    for (int k0 = 0; k0 < 256; k0 += 16) {
#pragma unroll
        for (int h = 0; h < 2; h++) {
            int r = lrow + h*64;
            float4 va = *(const float4*)(x + (size_t)(m0 + r)*256 + k0 + lk4);
            As[lk4+0][r] = va.x; As[lk4+1][r] = va.y; As[lk4+2][r] = va.z; As[lk4+3][r] = va.w;
            float4 vb = *(const float4*)(wsel + (size_t)(rb + r)*256 + k0 + lk4);
            Bs[lk4+0][r] = vb.x; Bs[lk4+1][r] = vb.y; Bs[lk4+2][r] = vb.z; Bs[lk4+3][r] = vb.w;
        }
        __syncthreads();
#pragma unroll
        for (int k = 0; k < 16; k++) {
            float a[8];
            *(float4*)&a[0] = *(const float4*)&As[k][ty*4];
            *(float4*)&a[4] = *(const float4*)&As[k][ty*4 + 64];
            ull b2[4];
            {
                ulonglong2 u0 = *(const ulonglong2*)&Bs[k][tx*4];
                ulonglong2 u1 = *(const ulonglong2*)&Bs[k][tx*4 + 64];
                b2[0] = u0.x; b2[1] = u0.y; b2[2] = u1.x; b2[3] = u1.y;
            }
            ull a2[8];
#pragma unroll
            for (int ii = 0; ii < 8; ii++) a2[ii] = pack2(a[ii], a[ii]);
#pragma unroll
            for (int ii = 0; ii < 8; ii++)
#pragma unroll
                for (int jj = 0; jj < 4; jj++) fma2(acc2[ii][jj], a2[ii], b2[jj]);
        }
        __syncthreads();
    }
    float bias[8];
#pragma unroll
    for (int jj = 0; jj < 8; jj++)
        bias[jj] = bsel[rb + tx*4 + ((jj >> 2) << 6) + (jj & 3)];
#pragma unroll
    for (int ii = 0; ii < 8; ii++) {
        int row = m0 + ty*4 + (ii & 3) + ((ii >> 2) << 6);
#pragma unroll
        for (int jh = 0; jh < 2; jh++) {
            float2 lo = unpack2(acc2[ii][jh*2]);
            float2 hi = unpack2(acc2[ii][jh*2+1]);
            float4 o = {lo.x + bias[jh*4], lo.y + bias[jh*4+1], hi.x + bias[jh*4+2], hi.y + bias[jh*4+3]};
            *(float4*)(dst + (size_t)row*256 + rb + tx*4 + (jh << 6)) = o;
        }
    }
}

// ---------------- BN1 stats: float4 gathers, 64 thr/point ----------------
__global__ __launch_bounds__(256) void k_stat1(const int* __restrict__ idx,
        const float* __restrict__ gp, const float* __restrict__ btp,
        const float* __restrict__ wp2, const float* __restrict__ bp2) {
    __shared__ float sR3[4][48];
    __shared__ int   sIdxs[4][16];
    __shared__ float sTmp[2048];
    const int t = threadIdx.x;
    const int sub = t >> 6, cg = t & 63, c0 = cg << 2;
    const float invM = 1.f / (float)MTOT;
    float bns[3], bnh[3];
#pragma unroll
    for (int d = 0; d < 3; d++) {
        float m = g_sum_p[d]*invM;
        float v = fmaxf(g_ssq_p[d]*invM - m*m, 0.f);
        bns[d] = gp[d]*rsqrtf(v+EPS); bnh[d] = btp[d] - m*bns[d];
    }
    float w20[4], w21[4], w22[4], bpc[4];
#pragma unroll
    for (int q = 0; q < 4; q++) {
        w20[q] = wp2[(c0+q)*3+0]; w21[q] = wp2[(c0+q)*3+1]; w22[q] = wp2[(c0+q)*3+2];
        bpc[q] = bp2[c0+q];
    }
    float s[4] = {0,0,0,0}, ss[4] = {0,0,0,0};
    const int i0 = blockIdx.x * 16;
    for (int it = 0; it < 4; it++) {
        const int i = i0 + it*4 + sub;
        __syncthreads();
        if (cg < 16) sIdxs[sub][cg] = idx[i*NS + cg];
        else if (cg < 32) {
            int j = cg - 16;
            const float* vp = g_v3 + ((size_t)i*NS + j)*3;
            sR3[sub][j*3+0] = fmaxf(bns[0]*vp[0] + bnh[0], 0.f);
            sR3[sub][j*3+1] = fmaxf(bns[1]*vp[1] + bnh[1], 0.f);
            sR3[sub][j*3+2] = fmaxf(bns[2]*vp[2] + bnh[2], 0.f);
        }
        __syncthreads();
        float4 xq4 = __ldg((const float4*)(g_xq + (size_t)i*C + c0));
#pragma unroll
        for (int j = 0; j < 16; j++) {
            int nb = sIdxs[sub][j];
            float r0 = sR3[sub][j*3], r1 = sR3[sub][j*3+1], r2 = sR3[sub][j*3+2];
            float4 xk4 = __ldg((const float4*)(g_xk + (size_t)nb*C + c0));
            float w;
            w = xk4.x - xq4.x + w20[0]*r0 + w21[0]*r1 + w22[0]*r2 + bpc[0]; s[0] += w; ss[0] += w*w;
            w = xk4.y - xq4.y + w20[1]*r0 + w21[1]*r1 + w22[1]*r2 + bpc[1]; s[1] += w; ss[1] += w*w;
            w = xk4.z - xq4.z + w20[2]*r0 + w21[2]*r1 + w22[2]*r2 + bpc[2]; s[2] += w; ss[2] += w*w;
            w = xk4.w - xq4.w + w20[3]*r0 + w21[3]*r1 + w22[3]*r2 + bpc[3]; s[3] += w; ss[3] += w*w;
        }
    }
    __syncthreads();
#pragma unroll
    for (int q = 0; q < 4; q++) {
        sTmp[sub*256 + c0 + q] = s[q];
        sTmp[1024 + sub*256 + c0 + q] = ss[q];
    }
    __syncthreads();
    float a = sTmp[t] + sTmp[256+t] + sTmp[512+t] + sTmp[768+t];
    atomicAdd(&g_sum_1[t], a);
    float b = sTmp[1024+t] + sTmp[1280+t] + sTmp[1536+t] + sTmp[1792+t];
    atomicAdd(&g_ssq_1[t], b);
}

// ---------------- w2: warp-specialized producer/consumer pipeline ----------------
// smem floats: sW[2][32*260]=16640 | sB[32*260]=8320   => 99.8 KB
#define K6_SMEM_FLOATS (16640 + 8320)
#define BAR_FULL0 1
#define BAR_EMPTY0 3
__global__ __launch_bounds__(256, 2) void k_w2(const int* __restrict__ idx,
        const float* __restrict__ gp, const float* __restrict__ btp,
        const float* __restrict__ wp2, const float* __restrict__ bp2,
        const float* __restrict__ ww1, const float* __restrict__ bw1,
        const float* __restrict__ g1, const float* __restrict__ b1) {
    extern __shared__ float sm[];
    float* sW = sm;            // 2 buffers of [32][260]
    float* sB = sm + 16640;    // [32][260]
    const int t = threadIdx.x;
    for (int e = t; e < 8192; e += 256) sB[(e>>8)*260 + (e&255)] = ww1[e];
    const float invM = 1.f / (float)MTOT;
    const int i0 = blockIdx.x * 32;
    float acs[4] = {0,0,0,0}, acss[4] = {0,0,0,0};
    __syncthreads();

    if (t < 128) {
        // ------- producer: gather xk, apply bn1(relu(bnp)) math, fill sW -------
        const int g = t >> 6, q = t & 63, c0 = q << 2;
        float bns[3], bnh[3];
#pragma unroll
        for (int d = 0; d < 3; d++) {
            float m = g_sum_p[d]*invM;
            float v = fmaxf(g_ssq_p[d]*invM - m*m, 0.f);
            bns[d] = gp[d]*rsqrtf(v+EPS); bnh[d] = btp[d] - m*bns[d];
        }
        float s1[4], h1[4], w20[4], w21[4], w22[4], bpc[4];
#pragma unroll
        for (int u = 0; u < 4; u++) {
            float mean = g_sum_1[c0+u]*invM;
            float var  = fmaxf(g_ssq_1[c0+u]*invM - mean*mean, 0.f);
            s1[u] = g1[c0+u]*rsqrtf(var+EPS); h1[u] = b1[c0+u] - mean*s1[u];
            w20[u] = wp2[(c0+u)*3+0]; w21[u] = wp2[(c0+u)*3+1]; w22[u] = wp2[(c0+u)*3+2];
            bpc[u] = bp2[c0+u];
        }
        for (int s = 0; s < 16; s++) {
            const int b = s & 1;
            if (s >= 2) bar_sync(BAR_EMPTY0 + b);
            const int iA = i0 + s*2;
            float* dst = sW + b*8320;
#pragma unroll 4
            for (int m = 0; m < 16; m++) {
                int row = m*2 + g;
                int pt = row >> 4, j = row & 15;
                int nb = __ldg(idx + (iA+pt)*NS + j);
                const float* vp = g_v3 + ((size_t)(iA+pt)*NS + j)*3;
                float r0 = fmaxf(bns[0]*__ldg(vp+0) + bnh[0], 0.f);
                float r1 = fmaxf(bns[1]*__ldg(vp+1) + bnh[1], 0.f);
                float r2 = fmaxf(bns[2]*__ldg(vp+2) + bnh[2], 0.f);
                float4 xk4 = __ldg((const float4*)(g_xk + (size_t)nb*C + c0));
                float4 xq4 = __ldg((const float4*)(g_xq + (size_t)(iA+pt)*C + c0));
                float4 u;
                u.x = fmaxf(s1[0]*(xk4.x - xq4.x + w20[0]*r0 + w21[0]*r1 + w22[0]*r2 + bpc[0]) + h1[0], 0.f);
                u.y = fmaxf(s1[1]*(xk4.y - xq4.y + w20[1]*r0 + w21[1]*r1 + w22[1]*r2 + bpc[1]) + h1[1], 0.f);
                u.z = fmaxf(s1[2]*(xk4.z - xq4.z + w20[2]*r0 + w21[2]*r1 + w22[2]*r2 + bpc[2]) + h1[2], 0.f);
                u.w = fmaxf(s1[3]*(xk4.w - xq4.w + w20[3]*r0 + w21[3]*r1 + w22[3]*r2 + bpc[3]) + h1[3], 0.f);
                *(float4*)(dst + row*260 + c0) = u;
            }
            bar_sync(BAR_FULL0 + b);   // both sides sync: drains STS, hands off
        }
    } else {
        // ------- consumer: FFMA2 GEMM (2 rows x 4 oc), STG, BN2 partials -------
        const int ct = t - 128;
        const int rg = ct >> 3, og = ct & 7;
        float bwv[4];
#pragma unroll
        for (int b = 0; b < 4; b++) bwv[b] = bw1[og + 8*b];
        for (int s = 0; s < 16; s++) {
            const int b = s & 1;
            bar_sync(BAR_FULL0 + b);
            const int iA = i0 + s*2;
            const float* src = sW + b*8320;
            ull a0[4] = {0,0,0,0}, a1[4] = {0,0,0,0};
            const ulonglong2* pa = (const ulonglong2*)(src + rg*260);
            const ulonglong2* pb = (const ulonglong2*)(src + (rg+16)*260);
            const ulonglong2* pw0 = (const ulonglong2*)(sB + og*260);
            const ulonglong2* pw1 = (const ulonglong2*)(sB + (og+8)*260);
            const ulonglong2* pw2 = (const ulonglong2*)(sB + (og+16)*260);
            const ulonglong2* pw3 = (const ulonglong2*)(sB + (og+24)*260);
#pragma unroll 8
            for (int k4 = 0; k4 < 64; k4++) {
                ulonglong2 av = pa[k4], bv = pb[k4];
                ulonglong2 w0 = pw0[k4];
                fma2(a0[0], av.x, w0.x); fma2(a0[0], av.y, w0.y);
                fma2(a1[0], bv.x, w0.x); fma2(a1[0], bv.y, w0.y);
                ulonglong2 w1 = pw1[k4];
                fma2(a0[1], av.x, w1.x); fma2(a0[1], av.y, w1.y);
                fma2(a1[1], bv.x, w1.x); fma2(a1[1], bv.y, w1.y);
                ulonglong2 w2 = pw2[k4];
                fma2(a0[2], av.x, w2.x); fma2(a0[2], av.y, w2.y);
                fma2(a1[2], bv.x, w2.x); fma2(a1[2], bv.y, w2.y);
                ulonglong2 w3 = pw3[k4];
                fma2(a0[3], av.x, w3.x); fma2(a0[3], av.y, w3.y);
                fma2(a1[3], bv.x, w3.x); fma2(a1[3], bv.y, w3.y);
            }
#pragma unroll
            for (int b2 = 0; b2 < 4; b2++) {
                int oc = og + 8*b2;
                float2 f0 = unpack2(a0[b2]);
                float v0 = f0.x + f0.y + bwv[b2];
                float2 f1 = unpack2(a1[b2]);
                float v1 = f1.x + f1.y + bwv[b2];
                g_w2[(size_t)iA*512 + rg*32 + oc] = v0;
                g_w2[(size_t)iA*512 + (rg+16)*32 + oc] = v1;
                acs[b2] += v0 + v1; acss[b2] += v0*v0 + v1*v1;
            }
            bar_arrive(BAR_EMPTY0 + b);
        }
    }
    // ------- BN2 stats reduce (reuse sW scratch) -------
    __syncthreads();
#pragma unroll
    for (int b = 0; b < 4; b++) {
        sW[t*4 + b] = acs[b];
        sW[1024 + t*4 + b] = acss[b];
    }
    __syncthreads();
    if (t < 32) {
        int g = t & 7, v = t >> 3;
        float a = 0.f, bb = 0.f;
#pragma unroll 8
        for (int u = 0; u < 32; u++) {
            a  += sW[(g + 8*u)*4 + v];
            bb += sW[1024 + (g + 8*u)*4 + v];
        }
        atomicAdd(&g_sum_2[t], a);
        atomicAdd(&g_ssq_2[t], bb);
    }
}

// ---------------- bn2->relu->ww2(regs)->softmax->weighted sum ----------------
__global__ __launch_bounds__(256) void k_out(const int* __restrict__ idx,
        const float* __restrict__ gp, const float* __restrict__ btp,
        const float* __restrict__ wp2, const float* __restrict__ bp2,
        const float* __restrict__ ww2, const float* __restrict__ bw2,
        const float* __restrict__ g2, const float* __restrict__ b2,
        float* __restrict__ out) {
    __shared__ float sU[32*34];
    __shared__ float sW3[32*33];
    __shared__ int   sIdx[32];
    __shared__ float sR3[96];
    const int t = threadIdx.x;
    const int cm = t & 31;
    const float invM = 1.f / (float)MTOT;
    float s2, h2;
    {
        float m = g_sum_2[cm]*invM;
        float v = fmaxf(g_ssq_2[cm]*invM - m*m, 0.f);
        s2 = g2[cm]*rsqrtf(v+EPS); h2 = b2[cm] - m*s2;
    }
    ull wreg[16];
    {
        const ulonglong2* wp = (const ulonglong2*)(ww2 + cm*32);
#pragma unroll
        for (int q = 0; q < 8; q++) {
            ulonglong2 v = __ldg(wp + q);
            wreg[q*2] = v.x; wreg[q*2+1] = v.y;
        }
    }
    const float bw2c = bw2[cm];
    float bns[3], bnh[3];
#pragma unroll
    for (int d = 0; d < 3; d++) {
        float m = g_sum_p[d]*invM;
        float v = fmaxf(g_ssq_p[d]*invM - m*m, 0.f);
        bns[d] = gp[d]*rsqrtf(v+EPS); bnh[d] = btp[d] - m*bns[d];
    }
    const float w20 = wp2[t*3+0], w21 = wp2[t*3+1], w22 = wp2[t*3+2], bpc = bp2[t];
    const int i0 = blockIdx.x * 16;

    for (int pp = 0; pp < 8; pp++) {
        const int iA = i0 + pp*2;
        __syncthreads();
        if (t < 32) sIdx[t] = idx[iA*NS + t];
        else if (t < 128) {
            int m = t - 32, d = m % 3;
            sR3[m] = fmaxf(bns[d]*g_v3[(size_t)iA*48 + m] + bnh[d], 0.f);
        }
#pragma unroll
        for (int rep = 0; rep < 4; rep++) {
            int linear = rep*256 + t;
            float v = g_w2[(size_t)iA*512 + linear];
            sU[(linear >> 5)*34 + cm] = fmaxf(s2*v + h2, 0.f);
        }
        __syncthreads();
#pragma unroll
        for (int rep = 0; rep < 4; rep++) {
            int jrow = rep*8 + (t >> 5);
            const ull* up = (const ull*)(sU + jrow*34);
            ull acc = 0ull;
#pragma unroll
            for (int k2 = 0; k2 < 16; k2++) fma2(acc, up[k2], wreg[k2]);
            float2 f = unpack2(acc);
            sW3[jrow*33 + cm] = f.x + f.y + bw2c;
        }
        __syncthreads();
        if (t < 64) {
            int pt = t >> 5, c = t & 31;
            int base = pt * 16;
            float mx = -1e30f;
#pragma unroll
            for (int j = 0; j < 16; j++) mx = fmaxf(mx, sW3[(base+j)*33 + c]);
            float sum = 0.f;
#pragma unroll
            for (int j = 0; j < 16; j++) {
                float e = __expf(sW3[(base+j)*33 + c] - mx);
                sW3[(base+j)*33 + c] = e; sum += e;
            }
            float inv = 1.f / sum;
#pragma unroll
            for (int j = 0; j < 16; j++) sW3[(base+j)*33 + c] *= inv;
        }
        __syncthreads();
#pragma unroll
        for (int pt = 0; pt < 2; pt++) {
            float acc = 0.f;
#pragma unroll
            for (int j = 0; j < 16; j++) {
                int rj = pt*16 + j;
                int nb = sIdx[rj];
                float pr = w20*sR3[rj*3] + w21*sR3[rj*3+1] + w22*sR3[rj*3+2] + bpc;
                acc += (g_xv[(size_t)nb*C + t] + pr) * sW3[rj*33 + cm];
            }
            out[(size_t)(iA+pt)*C + t] = acc;
        }
    }
}

extern "C" void kernel_launch(void* const* d_in, const int* in_sizes, int n_in,
                              void* d_out, int out_size) {
    const float* p   = (const float*)d_in[0];
    const float* x   = (const float*)d_in[1];
    const int*   idx = (const int*)d_in[2];
    const float* wq  = (const float*)d_in[3];
    const float* bq  = (const float*)d_in[4];
    const float* wk  = (const float*)d_in[5];
    const float* bk  = (const float*)d_in[6];
    const float* wv  = (const float*)d_in[7];
    const float* bv  = (const float*)d_in[8];
    const float* wp1 = (const float*)d_in[9];
    const float* bp1 = (const float*)d_in[10];
    const float* gp  = (const float*)d_in[11];
    const float* btp = (const float*)d_in[12];
    const float* wp2 = (const float*)d_in[13];
    const float* bp2 = (const float*)d_in[14];
    const float* g1  = (const float*)d_in[15];
    const float* b1  = (const float*)d_in[16];
    const float* ww1 = (const float*)d_in[17];
    const float* bw1 = (const float*)d_in[18];
    const float* g2  = (const float*)d_in[19];
    const float* b2  = (const float*)d_in[20];
    const float* ww2 = (const float*)d_in[21];
    const float* bw2 = (const float*)d_in[22];
    float* out = (float*)d_out;

    cudaFuncSetAttribute(k_w2, cudaFuncAttributeMaxDynamicSharedMemorySize,
                         K6_SMEM_FLOATS * (int)sizeof(float));

    k_zero<<<1, 256>>>();
    k_qkv_statp<<<dim3(7, 512), 256>>>(x, p, idx, wq, bq, wk, bk, wv, bv, wp1, bp1);
    k_stat1<<<4096, 256>>>(idx, gp, btp, wp2, bp2);
    k_w2<<<2048, 256, K6_SMEM_FLOATS * sizeof(float)>>>(idx, gp, btp, wp2, bp2, ww1, bw1, g1, b1);
    k_out<<<4096, 256>>>(idx, gp, btp, wp2, bp2, ww2, bw2, g2, b2, out);
}

// round 15
// speedup vs baseline: 1.1565x; 1.0098x over previous
#include <cuda_runtime.h>
#include <math.h>

#define NPTS 65536
#define NS 16
#define C 256
#define MTOT (NPTS*NS)
#define EPS 1e-5f

typedef unsigned long long ull;

__device__ __forceinline__ ull pack2(float lo, float hi) {
    ull r; asm("mov.b64 %0, {%1, %2};" : "=l"(r) : "f"(lo), "f"(hi)); return r;
}
__device__ __forceinline__ void fma2(ull& d, ull a, ull b) {
    asm("fma.rn.f32x2 %0, %1, %2, %3;" : "=l"(d) : "l"(a), "l"(b), "l"(d));
}
__device__ __forceinline__ float2 unpack2(ull v) {
    float2 f; asm("mov.b64 {%0, %1}, %2;" : "=f"(f.x), "=f"(f.y) : "l"(v)); return f;
}
__device__ __forceinline__ void bar_sync(int id) {
    asm volatile("bar.sync %0, %1;" :: "r"(id), "r"(256) : "memory");
}
__device__ __forceinline__ void bar_arrive(int id) {
    asm volatile("bar.arrive %0, %1;" :: "r"(id), "r"(256) : "memory");
}

__device__ float g_xq[NPTS*C];
__device__ float g_xk[NPTS*C];
__device__ float g_xv[NPTS*C];
__device__ float g_w2[NPTS*NS*32];
__device__ float g_v3[MTOT*3];
__device__ float g_sum_p[3], g_ssq_p[3];
__device__ float g_sum_1[C], g_ssq_1[C];
__device__ float g_sum_2[32], g_ssq_2[32];

__global__ void k_zero() {
    int t = threadIdx.x;
    if (t < 3)  { g_sum_p[t] = 0.f; g_ssq_p[t] = 0.f; }
    if (t < C)  { g_sum_1[t] = 0.f; g_ssq_1[t] = 0.f; }
    if (t < 32) { g_sum_2[t] = 0.f; g_ssq_2[t] = 0.f; }
}

// ---------------- qkv SGEMM (FFMA2) + fused statp/v3 ----------------
__global__ __launch_bounds__(256) void k_qkv_statp(
        const float* __restrict__ x, const float* __restrict__ p,
        const int* __restrict__ idx,
        const float* __restrict__ wq, const float* __restrict__ bq,
        const float* __restrict__ wk, const float* __restrict__ bk,
        const float* __restrict__ wv, const float* __restrict__ bv,
        const float* __restrict__ wp1, const float* __restrict__ bp1) {
    const int t = threadIdx.x;
    if (blockIdx.x == 6) {
        float W[9], B[3];
#pragma unroll
        for (int q = 0; q < 9; q++) W[q] = wp1[q];
#pragma unroll
        for (int q = 0; q < 3; q++) B[q] = bp1[q];
        float s[3] = {0,0,0}, ss[3] = {0,0,0};
        for (int m = blockIdx.y*256 + t; m < MTOT; m += 512*256) {
            int i = m >> 4;
            int nb = idx[m];
            float d0 = p[nb*3+0]-p[i*3+0], d1 = p[nb*3+1]-p[i*3+1], d2 = p[nb*3+2]-p[i*3+2];
#pragma unroll
            for (int d = 0; d < 3; d++) {
                float v = W[d*3+0]*d0 + W[d*3+1]*d1 + W[d*3+2]*d2 + B[d];
                g_v3[(size_t)m*3 + d] = v;
                s[d] += v; ss[d] += v*v;
            }
        }
#pragma unroll
        for (int off = 16; off > 0; off >>= 1)
#pragma unroll
            for (int d = 0; d < 3; d++) {
                s[d]  += __shfl_down_sync(0xffffffffu, s[d],  off);
                ss[d] += __shfl_down_sync(0xffffffffu, ss[d], off);
            }
        if ((t & 31) == 0)
#pragma unroll
            for (int d = 0; d < 3; d++) {
                atomicAdd(&g_sum_p[d], s[d]); atomicAdd(&g_ssq_p[d], ss[d]);
            }
        return;
    }
    __shared__ float As[16][132];
    __shared__ float Bs[16][132];
    const int tx = t & 15, ty = t >> 4;
    const int m0 = blockIdx.y * 128, n0 = blockIdx.x * 128;
    const float* wsel; const float* bsel; float* dst;
    if (n0 < 256)      { wsel = wq; bsel = bq; dst = g_xq; }
    else if (n0 < 512) { wsel = wk; bsel = bk; dst = g_xk; }
    else               { wsel = wv; bsel = bv; dst = g_xv; }
    const int rb = n0 & 255;
    ull acc2[8][4];
#pragma unroll
    for (int ii = 0; ii < 8; ii++)
#pragma unroll
        for (int jj = 0; jj < 4; jj++) acc2[ii][jj] = 0ull;
    const int lrow = t >> 2, lk4 = (t & 3) << 2;
    for (int k0 = 0; k0 < 256; k0 += 16) {
#pragma unroll
        for (int h = 0; h < 2; h++) {
            int r = lrow + h*64;
            float4 va = *(const float4*)(x + (size_t)(m0 + r)*256 + k0 + lk4);
            As[lk4+0][r] = va.x; As[lk4+1][r] = va.y; As[lk4+2][r] = va.z; As[lk4+3][r] = va.w;
            float4 vb = *(const float4*)(wsel + (size_t)(rb + r)*256 + k0 + lk4);
            Bs[lk4+0][r] = vb.x; Bs[lk4+1][r] = vb.y; Bs[lk4+2][r] = vb.z; Bs[lk4+3][r] = vb.w;
        }
        __syncthreads();
#pragma unroll
        for (int k = 0; k < 16; k++) {
            float a[8];
            *(float4*)&a[0] = *(const float4*)&As[k][ty*4];
            *(float4*)&a[4] = *(const float4*)&As[k][ty*4 + 64];
            ull b2[4];
            {
                ulonglong2 u0 = *(const ulonglong2*)&Bs[k][tx*4];
                ulonglong2 u1 = *(const ulonglong2*)&Bs[k][tx*4 + 64];
                b2[0] = u0.x; b2[1] = u0.y; b2[2] = u1.x; b2[3] = u1.y;
            }
            ull a2[8];
#pragma unroll
            for (int ii = 0; ii < 8; ii++) a2[ii] = pack2(a[ii], a[ii]);
#pragma unroll
            for (int ii = 0; ii < 8; ii++)
#pragma unroll
                for (int jj = 0; jj < 4; jj++) fma2(acc2[ii][jj], a2[ii], b2[jj]);
        }
        __syncthreads();
    }
    float bias[8];
#pragma unroll
    for (int jj = 0; jj < 8; jj++)
        bias[jj] = bsel[rb + tx*4 + ((jj >> 2) << 6) + (jj & 3)];
#pragma unroll
    for (int ii = 0; ii < 8; ii++) {
        int row = m0 + ty*4 + (ii & 3) + ((ii >> 2) << 6);
#pragma unroll
        for (int jh = 0; jh < 2; jh++) {
            float2 lo = unpack2(acc2[ii][jh*2]);
            float2 hi = unpack2(acc2[ii][jh*2+1]);
            float4 o = {lo.x + bias[jh*4], lo.y + bias[jh*4+1], hi.x + bias[jh*4+2], hi.y + bias[jh*4+3]};
            *(float4*)(dst + (size_t)row*256 + rb + tx*4 + (jh << 6)) = o;
        }
    }
}

// ---------------- BN1 stats: warp-autonomous, shfl metadata (bisect change) ----------------
__global__ __launch_bounds__(256) void k_stat1(const int* __restrict__ idx,
        const float* __restrict__ gp, const float* __restrict__ btp,
        const float* __restrict__ wp2, const float* __restrict__ bp2) {
    __shared__ float sTmp[2048];
    const int t = threadIdx.x;
    const int warp = t >> 5, lane = t & 31;
    const int half = warp & 1, ptw = warp >> 1;   // 4 point-slots
    const int c0 = half*128 + lane*4;
    const float invM = 1.f / (float)MTOT;
    float bns[3], bnh[3];
#pragma unroll
    for (int d = 0; d < 3; d++) {
        float m = g_sum_p[d]*invM;
        float v = fmaxf(g_ssq_p[d]*invM - m*m, 0.f);
        bns[d] = gp[d]*rsqrtf(v+EPS); bnh[d] = btp[d] - m*bns[d];
    }
    float w20[4], w21[4], w22[4], bpc[4];
#pragma unroll
    for (int q = 0; q < 4; q++) {
        w20[q] = wp2[(c0+q)*3+0]; w21[q] = wp2[(c0+q)*3+1]; w22[q] = wp2[(c0+q)*3+2];
        bpc[q] = bp2[c0+q];
    }
    float s[4] = {0,0,0,0}, ss[4] = {0,0,0,0};
    const int i0 = blockIdx.x * 16;
    const int lj = lane & 15;
    for (int it = 0; it < 4; it++) {
        const int i = i0 + it*4 + ptw;
        int nb_l = __ldg(idx + i*NS + lj);
        const float* vp = g_v3 + (size_t)i*48 + lj*3;
        float r0_l = fmaxf(bns[0]*__ldg(vp+0) + bnh[0], 0.f);
        float r1_l = fmaxf(bns[1]*__ldg(vp+1) + bnh[1], 0.f);
        float r2_l = fmaxf(bns[2]*__ldg(vp+2) + bnh[2], 0.f);
        float4 xq4 = __ldg((const float4*)(g_xq + (size_t)i*C + c0));
#pragma unroll
        for (int j = 0; j < 16; j++) {
            int nb = __shfl_sync(0xffffffffu, nb_l, j);
            float r0 = __shfl_sync(0xffffffffu, r0_l, j);
            float r1 = __shfl_sync(0xffffffffu, r1_l, j);
            float r2 = __shfl_sync(0xffffffffu, r2_l, j);
            float4 xk4 = __ldg((const float4*)(g_xk + (size_t)nb*C + c0));
            float w;
            w = xk4.x - xq4.x + w20[0]*r0 + w21[0]*r1 + w22[0]*r2 + bpc[0]; s[0] += w; ss[0] += w*w;
            w = xk4.y - xq4.y + w20[1]*r0 + w21[1]*r1 + w22[1]*r2 + bpc[1]; s[1] += w; ss[1] += w*w;
            w = xk4.z - xq4.z + w20[2]*r0 + w21[2]*r1 + w22[2]*r2 + bpc[2]; s[2] += w; ss[2] += w*w;
            w = xk4.w - xq4.w + w20[3]*r0 + w21[3]*r1 + w22[3]*r2 + bpc[3]; s[3] += w; ss[3] += w*w;
        }
    }
    __syncthreads();
#pragma unroll
    for (int q = 0; q < 4; q++) {
        sTmp[ptw*256 + c0 + q] = s[q];
        sTmp[1024 + ptw*256 + c0 + q] = ss[q];
    }
    __syncthreads();
    float a = sTmp[t] + sTmp[256+t] + sTmp[512+t] + sTmp[768+t];
    atomicAdd(&g_sum_1[t], a);
    float b = sTmp[1024+t] + sTmp[1280+t] + sTmp[1536+t] + sTmp[1792+t];
    atomicAdd(&g_ssq_1[t], b);
}

// ---------------- w2: warp-specialized pipeline (exact R11-passing version) ----------------
// smem floats: sW[2][32*260]=16640 | sB[32*260]=8320   => 99.8 KB
#define K6_SMEM_FLOATS (16640 + 8320)
#define BAR_FULL0 1
#define BAR_EMPTY0 3
__global__ __launch_bounds__(256, 2) void k_w2(const int* __restrict__ idx,
        const float* __restrict__ gp, const float* __restrict__ btp,
        const float* __restrict__ wp2, const float* __restrict__ bp2,
        const float* __restrict__ ww1, const float* __restrict__ bw1,
        const float* __restrict__ g1, const float* __restrict__ b1) {
    extern __shared__ float sm[];
    float* sW = sm;            // 2 buffers of [32][260]
    float* sB = sm + 16640;    // [32][260]
    const int t = threadIdx.x;
    for (int e = t; e < 8192; e += 256) sB[(e>>8)*260 + (e&255)] = ww1[e];
    const float invM = 1.f / (float)MTOT;
    const int i0 = blockIdx.x * 32;
    float acs[4] = {0,0,0,0}, acss[4] = {0,0,0,0};
    __syncthreads();

    if (t < 128) {
        // ------- producer: gather xk, apply bn1(relu(bnp)) math, fill sW -------
        const int g = t >> 6, q = t & 63, c0 = q << 2;
        float bns[3], bnh[3];
#pragma unroll
        for (int d = 0; d < 3; d++) {
            float m = g_sum_p[d]*invM;
            float v = fmaxf(g_ssq_p[d]*invM - m*m, 0.f);
            bns[d] = gp[d]*rsqrtf(v+EPS); bnh[d] = btp[d] - m*bns[d];
        }
        float s1[4], h1[4], w20[4], w21[4], w22[4], bpc[4];
#pragma unroll
        for (int u = 0; u < 4; u++) {
            float mean = g_sum_1[c0+u]*invM;
            float var  = fmaxf(g_ssq_1[c0+u]*invM - mean*mean, 0.f);
            s1[u] = g1[c0+u]*rsqrtf(var+EPS); h1[u] = b1[c0+u] - mean*s1[u];
            w20[u] = wp2[(c0+u)*3+0]; w21[u] = wp2[(c0+u)*3+1]; w22[u] = wp2[(c0+u)*3+2];
            bpc[u] = bp2[c0+u];
        }
        for (int s = 0; s < 16; s++) {
            const int b = s & 1;
            if (s >= 2) bar_sync(BAR_EMPTY0 + b);
            const int iA = i0 + s*2;
            float* dst = sW + b*8320;
#pragma unroll 4
            for (int m = 0; m < 16; m++) {
                int row = m*2 + g;
                int pt = row >> 4, j = row & 15;
                int nb = __ldg(idx + (iA+pt)*NS + j);
                const float* vp = g_v3 + ((size_t)(iA+pt)*NS + j)*3;
                float r0 = fmaxf(bns[0]*__ldg(vp+0) + bnh[0], 0.f);
                float r1 = fmaxf(bns[1]*__ldg(vp+1) + bnh[1], 0.f);
                float r2 = fmaxf(bns[2]*__ldg(vp+2) + bnh[2], 0.f);
                float4 xk4 = __ldg((const float4*)(g_xk + (size_t)nb*C + c0));
                float4 xq4 = __ldg((const float4*)(g_xq + (size_t)(iA+pt)*C + c0));
                float4 u;
                u.x = fmaxf(s1[0]*(xk4.x - xq4.x + w20[0]*r0 + w21[0]*r1 + w22[0]*r2 + bpc[0]) + h1[0], 0.f);
                u.y = fmaxf(s1[1]*(xk4.y - xq4.y + w20[1]*r0 + w21[1]*r1 + w22[1]*r2 + bpc[1]) + h1[1], 0.f);
                u.z = fmaxf(s1[2]*(xk4.z - xq4.z + w20[2]*r0 + w21[2]*r1 + w22[2]*r2 + bpc[2]) + h1[2], 0.f);
                u.w = fmaxf(s1[3]*(xk4.w - xq4.w + w20[3]*r0 + w21[3]*r1 + w22[3]*r2 + bpc[3]) + h1[3], 0.f);
                *(float4*)(dst + row*260 + c0) = u;
            }
            bar_sync(BAR_FULL0 + b);   // both sides sync: drains STS, hands off
        }
    } else {
        // ------- consumer: FFMA2 GEMM (2 rows x 4 oc), STG, BN2 partials -------
        const int ct = t - 128;
        const int rg = ct >> 3, og = ct & 7;
        float bwv[4];
#pragma unroll
        for (int b = 0; b < 4; b++) bwv[b] = bw1[og + 8*b];
        for (int s = 0; s < 16; s++) {
            const int b = s & 1;
            bar_sync(BAR_FULL0 + b);
            const int iA = i0 + s*2;
            const float* src = sW + b*8320;
            ull a0[4] = {0,0,0,0}, a1[4] = {0,0,0,0};
            const ulonglong2* pa = (const ulonglong2*)(src + rg*260);
            const ulonglong2* pb = (const ulonglong2*)(src + (rg+16)*260);
            const ulonglong2* pw0 = (const ulonglong2*)(sB + og*260);
            const ulonglong2* pw1 = (const ulonglong2*)(sB + (og+8)*260);
            const ulonglong2* pw2 = (const ulonglong2*)(sB + (og+16)*260);
            const ulonglong2* pw3 = (const ulonglong2*)(sB + (og+24)*260);
#pragma unroll 8
            for (int k4 = 0; k4 < 64; k4++) {
                ulonglong2 av = pa[k4], bv = pb[k4];
                ulonglong2 w0 = pw0[k4];
                fma2(a0[0], av.x, w0.x); fma2(a0[0], av.y, w0.y);
                fma2(a1[0], bv.x, w0.x); fma2(a1[0], bv.y, w0.y);
                ulonglong2 w1 = pw1[k4];
                fma2(a0[1], av.x, w1.x); fma2(a0[1], av.y, w1.y);
                fma2(a1[1], bv.x, w1.x); fma2(a1[1], bv.y, w1.y);
                ulonglong2 w2 = pw2[k4];
                fma2(a0[2], av.x, w2.x); fma2(a0[2], av.y, w2.y);
                fma2(a1[2], bv.x, w2.x); fma2(a1[2], bv.y, w2.y);
                ulonglong2 w3 = pw3[k4];
                fma2(a0[3], av.x, w3.x); fma2(a0[3], av.y, w3.y);
                fma2(a1[3], bv.x, w3.x); fma2(a1[3], bv.y, w3.y);
            }
#pragma unroll
            for (int b2 = 0; b2 < 4; b2++) {
                int oc = og + 8*b2;
                float2 f0 = unpack2(a0[b2]);
                float v0 = f0.x + f0.y + bwv[b2];
                float2 f1 = unpack2(a1[b2]);
                float v1 = f1.x + f1.y + bwv[b2];
                g_w2[(size_t)iA*512 + rg*32 + oc] = v0;
                g_w2[(size_t)iA*512 + (rg+16)*32 + oc] = v1;
                acs[b2] += v0 + v1; acss[b2] += v0*v0 + v1*v1;
            }
            bar_arrive(BAR_EMPTY0 + b);
        }
    }
    // ------- BN2 stats reduce (reuse sW scratch) -------
    __syncthreads();
#pragma unroll
    for (int b = 0; b < 4; b++) {
        sW[t*4 + b] = acs[b];
        sW[1024 + t*4 + b] = acss[b];
    }
    __syncthreads();
    if (t < 32) {
        int g = t & 7, v = t >> 3;
        float a = 0.f, bb = 0.f;
#pragma unroll 8
        for (int u = 0; u < 32; u++) {
            a  += sW[(g + 8*u)*4 + v];
            bb += sW[1024 + (g + 8*u)*4 + v];
        }
        atomicAdd(&g_sum_2[t], a);
        atomicAdd(&g_ssq_2[t], bb);
    }
}

// ---------------- bn2->relu->ww2(regs)->softmax->weighted sum ----------------
__global__ __launch_bounds__(256) void k_out(const int* __restrict__ idx,
        const float* __restrict__ gp, const float* __restrict__ btp,
        const float* __restrict__ wp2, const float* __restrict__ bp2,
        const float* __restrict__ ww2, const float* __restrict__ bw2,
        const float* __restrict__ g2, const float* __restrict__ b2,
        float* __restrict__ out) {
    __shared__ float sU[32*34];
    __shared__ float sW3[32*33];
    __shared__ int   sIdx[32];
    __shared__ float sR3[96];
    const int t = threadIdx.x;
    const int cm = t & 31;
    const float invM = 1.f / (float)MTOT;
    float s2, h2;
    {
        float m = g_sum_2[cm]*invM;
        float v = fmaxf(g_ssq_2[cm]*invM - m*m, 0.f);
        s2 = g2[cm]*rsqrtf(v+EPS); h2 = b2[cm] - m*s2;
    }
    ull wreg[16];
    {
        const ulonglong2* wp = (const ulonglong2*)(ww2 + cm*32);
#pragma unroll
        for (int q = 0; q < 8; q++) {
            ulonglong2 v = __ldg(wp + q);
            wreg[q*2] = v.x; wreg[q*2+1] = v.y;
        }
    }
    const float bw2c = bw2[cm];
    float bns[3], bnh[3];
#pragma unroll
    for (int d = 0; d < 3; d++) {
        float m = g_sum_p[d]*invM;
        float v = fmaxf(g_ssq_p[d]*invM - m*m, 0.f);
        bns[d] = gp[d]*rsqrtf(v+EPS); bnh[d] = btp[d] - m*bns[d];
    }
    const float w20 = wp2[t*3+0], w21 = wp2[t*3+1], w22 = wp2[t*3+2], bpc = bp2[t];
    const int i0 = blockIdx.x * 16;

    for (int pp = 0; pp < 8; pp++) {
        const int iA = i0 + pp*2;
        __syncthreads();
        if (t < 32) sIdx[t] = idx[iA*NS + t];
        else if (t < 128) {
            int m = t - 32, d = m % 3;
            sR3[m] = fmaxf(bns[d]*g_v3[(size_t)iA*48 + m] + bnh[d], 0.f);
        }
#pragma unroll
        for (int rep = 0; rep < 4; rep++) {
            int linear = rep*256 + t;
            float v = g_w2[(size_t)iA*512 + linear];
            sU[(linear >> 5)*34 + cm] = fmaxf(s2*v + h2, 0.f);
        }
        __syncthreads();
#pragma unroll
        for (int rep = 0; rep < 4; rep++) {
            int jrow = rep*8 + (t >> 5);
            const ull* up = (const ull*)(sU + jrow*34);
            ull acc = 0ull;
#pragma unroll
            for (int k2 = 0; k2 < 16; k2++) fma2(acc, up[k2], wreg[k2]);
            float2 f = unpack2(acc);
            sW3[jrow*33 + cm] = f.x + f.y + bw2c;
        }
        __syncthreads();
        if (t < 64) {
            int pt = t >> 5, c = t & 31;
            int base = pt * 16;
            float mx = -1e30f;
#pragma unroll
            for (int j = 0; j < 16; j++) mx = fmaxf(mx, sW3[(base+j)*33 + c]);
            float sum = 0.f;
#pragma unroll
            for (int j = 0; j < 16; j++) {
                float e = __expf(sW3[(base+j)*33 + c] - mx);
                sW3[(base+j)*33 + c] = e; sum += e;
            }
            float inv = 1.f / sum;
#pragma unroll
            for (int j = 0; j < 16; j++) sW3[(base+j)*33 + c] *= inv;
        }
        __syncthreads();
#pragma unroll
        for (int pt = 0; pt < 2; pt++) {
            float acc = 0.f;
#pragma unroll
            for (int j = 0; j < 16; j++) {
                int rj = pt*16 + j;
                int nb = sIdx[rj];
                float pr = w20*sR3[rj*3] + w21*sR3[rj*3+1] + w22*sR3[rj*3+2] + bpc;
                acc += (g_xv[(size_t)nb*C + t] + pr) * sW3[rj*33 + cm];
            }
            out[(size_t)(iA+pt)*C + t] = acc;
        }
    }
}

extern "C" void kernel_launch(void* const* d_in, const int* in_sizes, int n_in,
                              void* d_out, int out_size) {
    const float* p   = (const float*)d_in[0];
    const float* x   = (const float*)d_in[1];
    const int*   idx = (const int*)d_in[2];
    const float* wq  = (const float*)d_in[3];
    const float* bq  = (const float*)d_in[4];
    const float* wk  = (const float*)d_in[5];
    const float* bk  = (const float*)d_in[6];
    const float* wv  = (const float*)d_in[7];
    const float* bv  = (const float*)d_in[8];
    const float* wp1 = (const float*)d_in[9];
    const float* bp1 = (const float*)d_in[10];
    const float* gp  = (const float*)d_in[11];
    const float* btp = (const float*)d_in[12];
    const float* wp2 = (const float*)d_in[13];
    const float* bp2 = (const float*)d_in[14];
    const float* g1  = (const float*)d_in[15];
    const float* b1  = (const float*)d_in[16];
    const float* ww1 = (const float*)d_in[17];
    const float* bw1 = (const float*)d_in[18];
    const float* g2  = (const float*)d_in[19];
    const float* b2  = (const float*)d_in[20];
    const float* ww2 = (const float*)d_in[21];
    const float* bw2 = (const float*)d_in[22];
    float* out = (float*)d_out;

    cudaFuncSetAttribute(k_w2, cudaFuncAttributeMaxDynamicSharedMemorySize,
                         K6_SMEM_FLOATS * (int)sizeof(float));

    k_zero<<<1, 256>>>();
    k_qkv_statp<<<dim3(7, 512), 256>>>(x, p, idx, wq, bq, wk, bk, wv, bv, wp1, bp1);
    k_stat1<<<4096, 256>>>(idx, gp, btp, wp2, bp2);
    k_w2<<<2048, 256, K6_SMEM_FLOATS * sizeof(float)>>>(idx, gp, btp, wp2, bp2, ww1, bw1, g1, b1);
    k_out<<<4096, 256>>>(idx, gp, btp, wp2, bp2, ww2, bw2, g2, b2, out);
}

// round 16
// speedup vs baseline: 1.1696x; 1.0114x over previous
#include <cuda_runtime.h>
#include <math.h>

#define NPTS 65536
#define NS 16
#define C 256
#define MTOT (NPTS*NS)
#define EPS 1e-5f

typedef unsigned long long ull;

__device__ __forceinline__ ull pack2(float lo, float hi) {
    ull r; asm("mov.b64 %0, {%1, %2};" : "=l"(r) : "f"(lo), "f"(hi)); return r;
}
__device__ __forceinline__ void fma2(ull& d, ull a, ull b) {
    asm("fma.rn.f32x2 %0, %1, %2, %3;" : "=l"(d) : "l"(a), "l"(b), "l"(d));
}
__device__ __forceinline__ float2 unpack2(ull v) {
    float2 f; asm("mov.b64 {%0, %1}, %2;" : "=f"(f.x), "=f"(f.y) : "l"(v)); return f;
}
__device__ __forceinline__ void bar_sync(int id) {
    asm volatile("bar.sync %0, %1;" :: "r"(id), "r"(256) : "memory");
}
__device__ __forceinline__ void bar_arrive(int id) {
    asm volatile("bar.arrive %0, %1;" :: "r"(id), "r"(256) : "memory");
}

__device__ float g_xq[NPTS*C];
__device__ float g_xk[NPTS*C];
__device__ float g_xv[NPTS*C];
__device__ float g_w2[NPTS*NS*32];
__device__ float g_v3[MTOT*3];
__device__ float g_sum_p[3], g_ssq_p[3];
__device__ float g_sum_1[C], g_ssq_1[C];
__device__ float g_sum_2[32], g_ssq_2[32];

__global__ void k_zero() {
    int t = threadIdx.x;
    if (t < 3)  { g_sum_p[t] = 0.f; g_ssq_p[t] = 0.f; }
    if (t < C)  { g_sum_1[t] = 0.f; g_ssq_1[t] = 0.f; }
    if (t < 32) { g_sum_2[t] = 0.f; g_ssq_2[t] = 0.f; }
}

// ---------------- qkv SGEMM (FFMA2) + fused statp/v3 ----------------
__global__ __launch_bounds__(256) void k_qkv_statp(
        const float* __restrict__ x, const float* __restrict__ p,
        const int* __restrict__ idx,
        const float* __restrict__ wq, const float* __restrict__ bq,
        const float* __restrict__ wk, const float* __restrict__ bk,
        const float* __restrict__ wv, const float* __restrict__ bv,
        const float* __restrict__ wp1, const float* __restrict__ bp1) {
    const int t = threadIdx.x;
    if (blockIdx.x == 6) {
        float W[9], B[3];
#pragma unroll
        for (int q = 0; q < 9; q++) W[q] = wp1[q];
#pragma unroll
        for (int q = 0; q < 3; q++) B[q] = bp1[q];
        float s[3] = {0,0,0}, ss[3] = {0,0,0};
        for (int m = blockIdx.y*256 + t; m < MTOT; m += 512*256) {
            int i = m >> 4;
            int nb = idx[m];
            float d0 = p[nb*3+0]-p[i*3+0], d1 = p[nb*3+1]-p[i*3+1], d2 = p[nb*3+2]-p[i*3+2];
#pragma unroll
            for (int d = 0; d < 3; d++) {
                float v = W[d*3+0]*d0 + W[d*3+1]*d1 + W[d*3+2]*d2 + B[d];
                g_v3[(size_t)m*3 + d] = v;
                s[d] += v; ss[d] += v*v;
            }
        }
#pragma unroll
        for (int off = 16; off > 0; off >>= 1)
#pragma unroll
            for (int d = 0; d < 3; d++) {
                s[d]  += __shfl_down_sync(0xffffffffu, s[d],  off);
                ss[d] += __shfl_down_sync(0xffffffffu, ss[d], off);
            }
        if ((t & 31) == 0)
#pragma unroll
            for (int d = 0; d < 3; d++) {
                atomicAdd(&g_sum_p[d], s[d]); atomicAdd(&g_ssq_p[d], ss[d]);
            }
        return;
    }
    __shared__ float As[16][132];
    __shared__ float Bs[16][132];
    const int tx = t & 15, ty = t >> 4;
    const int m0 = blockIdx.y * 128, n0 = blockIdx.x * 128;
    const float* wsel; const float* bsel; float* dst;
    if (n0 < 256)      { wsel = wq; bsel = bq; dst = g_xq; }
    else if (n0 < 512) { wsel = wk; bsel = bk; dst = g_xk; }
    else               { wsel = wv; bsel = bv; dst = g_xv; }
    const int rb = n0 & 255;
    ull acc2[8][4];
#pragma unroll
    for (int ii = 0; ii < 8; ii++)
#pragma unroll
        for (int jj = 0; jj < 4; jj++) acc2[ii][jj] = 0ull;
    const int lrow = t >> 2, lk4 = (t & 3) << 2;
    for (int k0 = 0; k0 < 256; k0 += 16) {
#pragma unroll
        for (int h = 0; h < 2; h++) {
            int r = lrow + h*64;
            float4 va = *(const float4*)(x + (size_t)(m0 + r)*256 + k0 + lk4);
            As[lk4+0][r] = va.x; As[lk4+1][r] = va.y; As[lk4+2][r] = va.z; As[lk4+3][r] = va.w;
            float4 vb = *(const float4*)(wsel + (size_t)(rb + r)*256 + k0 + lk4);
            Bs[lk4+0][r] = vb.x; Bs[lk4+1][r] = vb.y; Bs[lk4+2][r] = vb.z; Bs[lk4+3][r] = vb.w;
        }
        __syncthreads();
#pragma unroll
        for (int k = 0; k < 16; k++) {
            float a[8];
            *(float4*)&a[0] = *(const float4*)&As[k][ty*4];
            *(float4*)&a[4] = *(const float4*)&As[k][ty*4 + 64];
            ull b2[4];
            {
                ulonglong2 u0 = *(const ulonglong2*)&Bs[k][tx*4];
                ulonglong2 u1 = *(const ulonglong2*)&Bs[k][tx*4 + 64];
                b2[0] = u0.x; b2[1] = u0.y; b2[2] = u1.x; b2[3] = u1.y;
            }
            ull a2[8];
#pragma unroll
            for (int ii = 0; ii < 8; ii++) a2[ii] = pack2(a[ii], a[ii]);
#pragma unroll
            for (int ii = 0; ii < 8; ii++)
#pragma unroll
                for (int jj = 0; jj < 4; jj++) fma2(acc2[ii][jj], a2[ii], b2[jj]);
        }
        __syncthreads();
    }
    float bias[8];
#pragma unroll
    for (int jj = 0; jj < 8; jj++)
        bias[jj] = bsel[rb + tx*4 + ((jj >> 2) << 6) + (jj & 3)];
#pragma unroll
    for (int ii = 0; ii < 8; ii++) {
        int row = m0 + ty*4 + (ii & 3) + ((ii >> 2) << 6);
#pragma unroll
        for (int jh = 0; jh < 2; jh++) {
            float2 lo = unpack2(acc2[ii][jh*2]);
            float2 hi = unpack2(acc2[ii][jh*2+1]);
            float4 o = {lo.x + bias[jh*4], lo.y + bias[jh*4+1], hi.x + bias[jh*4+2], hi.y + bias[jh*4+3]};
            *(float4*)(dst + (size_t)row*256 + rb + tx*4 + (jh << 6)) = o;
        }
    }
}

// ---------------- BN1 stats: warp-autonomous, shfl metadata ----------------
__global__ __launch_bounds__(256) void k_stat1(const int* __restrict__ idx,
        const float* __restrict__ gp, const float* __restrict__ btp,
        const float* __restrict__ wp2, const float* __restrict__ bp2) {
    __shared__ float sTmp[2048];
    const int t = threadIdx.x;
    const int warp = t >> 5, lane = t & 31;
    const int half = warp & 1, ptw = warp >> 1;
    const int c0 = half*128 + lane*4;
    const float invM = 1.f / (float)MTOT;
    float bns[3], bnh[3];
#pragma unroll
    for (int d = 0; d < 3; d++) {
        float m = g_sum_p[d]*invM;
        float v = fmaxf(g_ssq_p[d]*invM - m*m, 0.f);
        bns[d] = gp[d]*rsqrtf(v+EPS); bnh[d] = btp[d] - m*bns[d];
    }
    float w20[4], w21[4], w22[4], bpc[4];
#pragma unroll
    for (int q = 0; q < 4; q++) {
        w20[q] = wp2[(c0+q)*3+0]; w21[q] = wp2[(c0+q)*3+1]; w22[q] = wp2[(c0+q)*3+2];
        bpc[q] = bp2[c0+q];
    }
    float s[4] = {0,0,0,0}, ss[4] = {0,0,0,0};
    const int i0 = blockIdx.x * 16;
    const int lj = lane & 15;
    for (int it = 0; it < 4; it++) {
        const int i = i0 + it*4 + ptw;
        int nb_l = __ldg(idx + i*NS + lj);
        const float* vp = g_v3 + (size_t)i*48 + lj*3;
        float r0_l = fmaxf(bns[0]*__ldg(vp+0) + bnh[0], 0.f);
        float r1_l = fmaxf(bns[1]*__ldg(vp+1) + bnh[1], 0.f);
        float r2_l = fmaxf(bns[2]*__ldg(vp+2) + bnh[2], 0.f);
        float4 xq4 = __ldg((const float4*)(g_xq + (size_t)i*C + c0));
#pragma unroll
        for (int j = 0; j < 16; j++) {
            int nb = __shfl_sync(0xffffffffu, nb_l, j);
            float r0 = __shfl_sync(0xffffffffu, r0_l, j);
            float r1 = __shfl_sync(0xffffffffu, r1_l, j);
            float r2 = __shfl_sync(0xffffffffu, r2_l, j);
            float4 xk4 = __ldg((const float4*)(g_xk + (size_t)nb*C + c0));
            float w;
            w = xk4.x - xq4.x + w20[0]*r0 + w21[0]*r1 + w22[0]*r2 + bpc[0]; s[0] += w; ss[0] += w*w;
            w = xk4.y - xq4.y + w20[1]*r0 + w21[1]*r1 + w22[1]*r2 + bpc[1]; s[1] += w; ss[1] += w*w;
            w = xk4.z - xq4.z + w20[2]*r0 + w21[2]*r1 + w22[2]*r2 + bpc[2]; s[2] += w; ss[2] += w*w;
            w = xk4.w - xq4.w + w20[3]*r0 + w21[3]*r1 + w22[3]*r2 + bpc[3]; s[3] += w; ss[3] += w*w;
        }
    }
    __syncthreads();
#pragma unroll
    for (int q = 0; q < 4; q++) {
        sTmp[ptw*256 + c0 + q] = s[q];
        sTmp[1024 + ptw*256 + c0 + q] = ss[q];
    }
    __syncthreads();
    float a = sTmp[t] + sTmp[256+t] + sTmp[512+t] + sTmp[768+t];
    atomicAdd(&g_sum_1[t], a);
    float b = sTmp[1024+t] + sTmp[1280+t] + sTmp[1536+t] + sTmp[1792+t];
    atomicAdd(&g_ssq_1[t], b);
}

// ---------------- w2: warp-specialized pipeline, shfl-metadata producer ----------------
// smem floats: sW[2][32*260]=16640 | sB[32*260]=8320   => 99.8 KB
#define K6_SMEM_FLOATS (16640 + 8320)
#define BAR_FULL0 1
#define BAR_EMPTY0 3
__global__ __launch_bounds__(256, 2) void k_w2(const int* __restrict__ idx,
        const float* __restrict__ gp, const float* __restrict__ btp,
        const float* __restrict__ wp2, const float* __restrict__ bp2,
        const float* __restrict__ ww1, const float* __restrict__ bw1,
        const float* __restrict__ g1, const float* __restrict__ b1) {
    extern __shared__ float sm[];
    float* sW = sm;            // 2 buffers of [32][260]
    float* sB = sm + 16640;    // [32][260]
    const int t = threadIdx.x;
    for (int e = t; e < 8192; e += 256) sB[(e>>8)*260 + (e&255)] = ww1[e];
    const float invM = 1.f / (float)MTOT;
    const int i0 = blockIdx.x * 32;
    float acs[4] = {0,0,0,0}, acss[4] = {0,0,0,0};
    __syncthreads();

    if (t < 128) {
        // ------- producer: prelude+shfl metadata, hoisted xq, gather xk -------
        const int g = t >> 6, q = t & 63, c0 = q << 2;
        const int lane = t & 31;
        float bns[3], bnh[3];
#pragma unroll
        for (int d = 0; d < 3; d++) {
            float m = g_sum_p[d]*invM;
            float v = fmaxf(g_ssq_p[d]*invM - m*m, 0.f);
            bns[d] = gp[d]*rsqrtf(v+EPS); bnh[d] = btp[d] - m*bns[d];
        }
        float s1[4], h1[4], w20[4], w21[4], w22[4], bpc[4];
#pragma unroll
        for (int u = 0; u < 4; u++) {
            float mean = g_sum_1[c0+u]*invM;
            float var  = fmaxf(g_ssq_1[c0+u]*invM - mean*mean, 0.f);
            s1[u] = g1[c0+u]*rsqrtf(var+EPS); h1[u] = b1[c0+u] - mean*s1[u];
            w20[u] = wp2[(c0+u)*3+0]; w21[u] = wp2[(c0+u)*3+1]; w22[u] = wp2[(c0+u)*3+2];
            bpc[u] = bp2[c0+u];
        }
        for (int s = 0; s < 16; s++) {
            const int b = s & 1;
            if (s >= 2) bar_sync(BAR_EMPTY0 + b);
            const int iA = i0 + s*2;
            // prelude: lane l owns row l (rows 0..15 = point iA, 16..31 = point iA+1)
            int nb_l = __ldg(idx + iA*NS + lane);
            const float* vp = g_v3 + (size_t)iA*48 + lane*3;
            float r0_l = fmaxf(bns[0]*__ldg(vp+0) + bnh[0], 0.f);
            float r1_l = fmaxf(bns[1]*__ldg(vp+1) + bnh[1], 0.f);
            float r2_l = fmaxf(bns[2]*__ldg(vp+2) + bnh[2], 0.f);
            float4 xqA = __ldg((const float4*)(g_xq + (size_t)iA*C + c0));
            float4 xqB = __ldg((const float4*)(g_xq + (size_t)(iA+1)*C + c0));
            float* dst = sW + b*8320;
#pragma unroll 4
            for (int m = 0; m < 16; m++) {
                int row = m*2 + g;
                int nb = __shfl_sync(0xffffffffu, nb_l, row);
                float r0 = __shfl_sync(0xffffffffu, r0_l, row);
                float r1 = __shfl_sync(0xffffffffu, r1_l, row);
                float r2 = __shfl_sync(0xffffffffu, r2_l, row);
                float4 xk4 = __ldg((const float4*)(g_xk + (size_t)nb*C + c0));
                float4 xq4 = (m < 8) ? xqA : xqB;
                float4 u;
                u.x = fmaxf(s1[0]*(xk4.x - xq4.x + w20[0]*r0 + w21[0]*r1 + w22[0]*r2 + bpc[0]) + h1[0], 0.f);
                u.y = fmaxf(s1[1]*(xk4.y - xq4.y + w20[1]*r0 + w21[1]*r1 + w22[1]*r2 + bpc[1]) + h1[1], 0.f);
                u.z = fmaxf(s1[2]*(xk4.z - xq4.z + w20[2]*r0 + w21[2]*r1 + w22[2]*r2 + bpc[2]) + h1[2], 0.f);
                u.w = fmaxf(s1[3]*(xk4.w - xq4.w + w20[3]*r0 + w21[3]*r1 + w22[3]*r2 + bpc[3]) + h1[3], 0.f);
                *(float4*)(dst + row*260 + c0) = u;
            }
            bar_sync(BAR_FULL0 + b);
        }
    } else {
        // ------- consumer: FFMA2 GEMM (2 rows x 4 oc), STG, BN2 partials -------
        const int ct = t - 128;
        const int rg = ct >> 3, og = ct & 7;
        float bwv[4];
#pragma unroll
        for (int b = 0; b < 4; b++) bwv[b] = bw1[og + 8*b];
        for (int s = 0; s < 16; s++) {
            const int b = s & 1;
            bar_sync(BAR_FULL0 + b);
            const int iA = i0 + s*2;
            const float* src = sW + b*8320;
            ull a0[4] = {0,0,0,0}, a1[4] = {0,0,0,0};
            const ulonglong2* pa = (const ulonglong2*)(src + rg*260);
            const ulonglong2* pb = (const ulonglong2*)(src + (rg+16)*260);
            const ulonglong2* pw0 = (const ulonglong2*)(sB + og*260);
            const ulonglong2* pw1 = (const ulonglong2*)(sB + (og+8)*260);
            const ulonglong2* pw2 = (const ulonglong2*)(sB + (og+16)*260);
            const ulonglong2* pw3 = (const ulonglong2*)(sB + (og+24)*260);
#pragma unroll 8
            for (int k4 = 0; k4 < 64; k4++) {
                ulonglong2 av = pa[k4], bv = pb[k4];
                ulonglong2 w0 = pw0[k4];
                fma2(a0[0], av.x, w0.x); fma2(a0[0], av.y, w0.y);
                fma2(a1[0], bv.x, w0.x); fma2(a1[0], bv.y, w0.y);
                ulonglong2 w1 = pw1[k4];
                fma2(a0[1], av.x, w1.x); fma2(a0[1], av.y, w1.y);
                fma2(a1[1], bv.x, w1.x); fma2(a1[1], bv.y, w1.y);
                ulonglong2 w2 = pw2[k4];
                fma2(a0[2], av.x, w2.x); fma2(a0[2], av.y, w2.y);
                fma2(a1[2], bv.x, w2.x); fma2(a1[2], bv.y, w2.y);
                ulonglong2 w3 = pw3[k4];
                fma2(a0[3], av.x, w3.x); fma2(a0[3], av.y, w3.y);
                fma2(a1[3], bv.x, w3.x); fma2(a1[3], bv.y, w3.y);
            }
#pragma unroll
            for (int b2 = 0; b2 < 4; b2++) {
                int oc = og + 8*b2;
                float2 f0 = unpack2(a0[b2]);
                float v0 = f0.x + f0.y + bwv[b2];
                float2 f1 = unpack2(a1[b2]);
                float v1 = f1.x + f1.y + bwv[b2];
                g_w2[(size_t)iA*512 + rg*32 + oc] = v0;
                g_w2[(size_t)iA*512 + (rg+16)*32 + oc] = v1;
                acs[b2] += v0 + v1; acss[b2] += v0*v0 + v1*v1;
            }
            bar_arrive(BAR_EMPTY0 + b);
        }
    }
    // ------- BN2 stats reduce (reuse sW scratch) -------
    __syncthreads();
#pragma unroll
    for (int b = 0; b < 4; b++) {
        sW[t*4 + b] = acs[b];
        sW[1024 + t*4 + b] = acss[b];
    }
    __syncthreads();
    if (t < 32) {
        int g = t & 7, v = t >> 3;
        float a = 0.f, bb = 0.f;
#pragma unroll 8
        for (int u = 0; u < 32; u++) {
            a  += sW[(g + 8*u)*4 + v];
            bb += sW[1024 + (g + 8*u)*4 + v];
        }
        atomicAdd(&g_sum_2[t], a);
        atomicAdd(&g_ssq_2[t], bb);
    }
}

// ---------------- bn2->relu->ww2(regs)->softmax->weighted sum ----------------
__global__ __launch_bounds__(256) void k_out(const int* __restrict__ idx,
        const float* __restrict__ gp, const float* __restrict__ btp,
        const float* __restrict__ wp2, const float* __restrict__ bp2,
        const float* __restrict__ ww2, const float* __restrict__ bw2,
        const float* __restrict__ g2, const float* __restrict__ b2,
        float* __restrict__ out) {
    __shared__ float sU[32*34];
    __shared__ float sW3[32*33];
    __shared__ int   sIdx[32];
    __shared__ float sR3[96];
    const int t = threadIdx.x;
    const int cm = t & 31;
    const float invM = 1.f / (float)MTOT;
    float s2, h2;
    {
        float m = g_sum_2[cm]*invM;
        float v = fmaxf(g_ssq_2[cm]*invM - m*m, 0.f);
        s2 = g2[cm]*rsqrtf(v+EPS); h2 = b2[cm] - m*s2;
    }
    ull wreg[16];
    {
        const ulonglong2* wp = (const ulonglong2*)(ww2 + cm*32);
#pragma unroll
        for (int q = 0; q < 8; q++) {
            ulonglong2 v = __ldg(wp + q);
            wreg[q*2] = v.x; wreg[q*2+1] = v.y;
        }
    }
    const float bw2c = bw2[cm];
    float bns[3], bnh[3];
#pragma unroll
    for (int d = 0; d < 3; d++) {
        float m = g_sum_p[d]*invM;
        float v = fmaxf(g_ssq_p[d]*invM - m*m, 0.f);
        bns[d] = gp[d]*rsqrtf(v+EPS); bnh[d] = btp[d] - m*bns[d];
    }
    const float w20 = wp2[t*3+0], w21 = wp2[t*3+1], w22 = wp2[t*3+2], bpc = bp2[t];
    const int i0 = blockIdx.x * 16;

    for (int pp = 0; pp < 8; pp++) {
        const int iA = i0 + pp*2;
        __syncthreads();
        if (t < 32) sIdx[t] = idx[iA*NS + t];
        else if (t < 128) {
            int m = t - 32, d = m % 3;
            sR3[m] = fmaxf(bns[d]*g_v3[(size_t)iA*48 + m] + bnh[d], 0.f);
        }
#pragma unroll
        for (int rep = 0; rep < 4; rep++) {
            int linear = rep*256 + t;
            float v = g_w2[(size_t)iA*512 + linear];
            sU[(linear >> 5)*34 + cm] = fmaxf(s2*v + h2, 0.f);
        }
        __syncthreads();
#pragma unroll
        for (int rep = 0; rep < 4; rep++) {
            int jrow = rep*8 + (t >> 5);
            const ull* up = (const ull*)(sU + jrow*34);
            ull acc = 0ull;
#pragma unroll
            for (int k2 = 0; k2 < 16; k2++) fma2(acc, up[k2], wreg[k2]);
            float2 f = unpack2(acc);
            sW3[jrow*33 + cm] = f.x + f.y + bw2c;
        }
        __syncthreads();
        if (t < 64) {
            int pt = t >> 5, c = t & 31;
            int base = pt * 16;
            float mx = -1e30f;
#pragma unroll
            for (int j = 0; j < 16; j++) mx = fmaxf(mx, sW3[(base+j)*33 + c]);
            float sum = 0.f;
#pragma unroll
            for (int j = 0; j < 16; j++) {
                float e = __expf(sW3[(base+j)*33 + c] - mx);
                sW3[(base+j)*33 + c] = e; sum += e;
            }
            float inv = 1.f / sum;
#pragma unroll
            for (int j = 0; j < 16; j++) sW3[(base+j)*33 + c] *= inv;
        }
        __syncthreads();
#pragma unroll
        for (int pt = 0; pt < 2; pt++) {
            float acc = 0.f;
#pragma unroll
            for (int j = 0; j < 16; j++) {
                int rj = pt*16 + j;
                int nb = sIdx[rj];
                float pr = w20*sR3[rj*3] + w21*sR3[rj*3+1] + w22*sR3[rj*3+2] + bpc;
                acc += (g_xv[(size_t)nb*C + t] + pr) * sW3[rj*33 + cm];
            }
            out[(size_t)(iA+pt)*C + t] = acc;
        }
    }
}

extern "C" void kernel_launch(void* const* d_in, const int* in_sizes, int n_in,
                              void* d_out, int out_size) {
    const float* p   = (const float*)d_in[0];
    const float* x   = (const float*)d_in[1];
    const int*   idx = (const int*)d_in[2];
    const float* wq  = (const float*)d_in[3];
    const float* bq  = (const float*)d_in[4];
    const float* wk  = (const float*)d_in[5];
    const float* bk  = (const float*)d_in[6];
    const float* wv  = (const float*)d_in[7];
    const float* bv  = (const float*)d_in[8];
    const float* wp1 = (const float*)d_in[9];
    const float* bp1 = (const float*)d_in[10];
    const float* gp  = (const float*)d_in[11];
    const float* btp = (const float*)d_in[12];
    const float* wp2 = (const float*)d_in[13];
    const float* bp2 = (const float*)d_in[14];
    const float* g1  = (const float*)d_in[15];
    const float* b1  = (const float*)d_in[16];
    const float* ww1 = (const float*)d_in[17];
    const float* bw1 = (const float*)d_in[18];
    const float* g2  = (const float*)d_in[19];
    const float* b2  = (const float*)d_in[20];
    const float* ww2 = (const float*)d_in[21];
    const float* bw2 = (const float*)d_in[22];
    float* out = (float*)d_out;

    cudaFuncSetAttribute(k_w2, cudaFuncAttributeMaxDynamicSharedMemorySize,
                         K6_SMEM_FLOATS * (int)sizeof(float));

    k_zero<<<1, 256>>>();
    k_qkv_statp<<<dim3(7, 512), 256>>>(x, p, idx, wq, bq, wk, bk, wv, bv, wp1, bp1);
    k_stat1<<<4096, 256>>>(idx, gp, btp, wp2, bp2);
    k_w2<<<2048, 256, K6_SMEM_FLOATS * sizeof(float)>>>(idx, gp, btp, wp2, bp2, ww1, bw1, g1, b1);
    k_out<<<4096, 256>>>(idx, gp, btp, wp2, bp2, ww2, bw2, g2, b2, out);
}